// round 10
// baseline (speedup 1.0000x reference)
#include <cuda_runtime.h>
#include <cuda_fp16.h>
#include <cstdint>

#define NI 16384
#define IPB 64
#define NTHREADS 128
#define NBLK (NI / IPB)

// gemm kernel smem: X[64m][128k]f16 16KB @0, then b1/b2
#define XHO  0u
#define META 16384u
#define SMEM_BYTES 17664

__device__ uint4 g_w1f[4096];                         // W1 mma-B fragment image
__device__ uint4 g_w2f[2048];                         // W2 mma-B fragment image
__device__ __align__(16) unsigned char g_x[NI * 256]; // X rows, fp16 [16384][128]

static __device__ __forceinline__ uint32_t smem_u32(const void* p) {
    uint32_t a;
    asm("{ .reg .u64 t; cvta.to.shared.u64 t, %1; cvt.u32.u64 %0, t; }" : "=r"(a) : "l"(p));
    return a;
}
static __device__ __forceinline__ uint64_t gmem_u64(const void* p) {
    uint64_t a;
    asm("cvta.to.global.u64 %0, %1;" : "=l"(a) : "l"(p));
    return a;
}
static __device__ __forceinline__ uint32_t xoff(int m, int k) {   // 256B rows, swizzled
    return (uint32_t)(m * 256 + ((k * 2) ^ ((m & 7) * 16)));
}
static __device__ __forceinline__ uint32_t h2u(__half2 v) {
    return *reinterpret_cast<uint32_t*>(&v);
}
static __device__ __forceinline__ uint2 pack_h4(float4 v) {
    return make_uint2(h2u(__floats2half2_rn(v.x, v.y)), h2u(__floats2half2_rn(v.z, v.w)));
}
static __device__ __forceinline__ void cp16(uint32_t dst, uint64_t src) {
    asm volatile("cp.async.cg.shared.global [%0], [%1], 16;" :: "r"(dst), "l"(src) : "memory");
}
#define CP_COMMIT() asm volatile("cp.async.commit_group;" ::: "memory")
#define CP_WAIT0()  asm volatile("cp.async.wait_group 0;" ::: "memory")

static __device__ __forceinline__ void ldm_x4(uint32_t* r, uint32_t a) {
    asm volatile("ldmatrix.sync.aligned.m8n8.x4.shared.b16 {%0,%1,%2,%3}, [%4];"
        : "=r"(r[0]), "=r"(r[1]), "=r"(r[2]), "=r"(r[3]) : "r"(a));
}
static __device__ __forceinline__ void mma16816h(float* c, const uint32_t* a,
                                                 uint32_t b0, uint32_t b1) {
    asm volatile("mma.sync.aligned.m16n8k16.row.col.f32.f16.f16.f32 "
        "{%0,%1,%2,%3}, {%4,%5,%6,%7}, {%8,%9}, {%0,%1,%2,%3};"
        : "+f"(c[0]), "+f"(c[1]), "+f"(c[2]), "+f"(c[3])
        : "r"(a[0]), "r"(a[1]), "r"(a[2]), "r"(a[3]), "r"(b0), "r"(b1));
}

// ---- kernel A: streaming gather + (first 6144 threads) weight frag build ----
__global__ __launch_bounds__(256)
void gather_kernel(const int* __restrict__ item_ids,
                   const int* __restrict__ tag_ids,
                   const int* __restrict__ tag_lens,
                   const float* __restrict__ item_table,
                   const float* __restrict__ dat_table,
                   const float* __restrict__ tag_table,
                   const float* __restrict__ W1,
                   const float* __restrict__ W2,
                   float* __restrict__ out)
{
    const int t = blockIdx.x * 256 + threadIdx.x;   // 0 .. 262143

    if (t < 6144) {
        if (t < 4096) {
            const int kt = t >> 9, rem = t & 511;
            const int p = rem >> 5, lane = rem & 31;
            const int k0 = kt * 16 + (lane & 3) * 2;
            const int nA = p * 16 + (lane >> 2), nB = nA + 8;
            uint4 v;
            v.x = h2u(__floats2half2_rn(W1[(size_t)k0 * 256 + nA], W1[(size_t)(k0 + 1) * 256 + nA]));
            v.y = h2u(__floats2half2_rn(W1[(size_t)(k0 + 8) * 256 + nA], W1[(size_t)(k0 + 9) * 256 + nA]));
            v.z = h2u(__floats2half2_rn(W1[(size_t)k0 * 256 + nB], W1[(size_t)(k0 + 1) * 256 + nB]));
            v.w = h2u(__floats2half2_rn(W1[(size_t)(k0 + 8) * 256 + nB], W1[(size_t)(k0 + 9) * 256 + nB]));
            g_w1f[t] = v;
        } else {
            const int u = t - 4096;
            const int kt = u >> 7, rem = u & 127;
            const int p = rem >> 5, lane = rem & 31;
            const int k0 = kt * 16 + (lane & 3) * 2;
            const int nA = p * 16 + (lane >> 2), nB = nA + 8;
            uint4 v;
            v.x = h2u(__floats2half2_rn(W2[(size_t)k0 * 64 + nA], W2[(size_t)(k0 + 1) * 64 + nA]));
            v.y = h2u(__floats2half2_rn(W2[(size_t)(k0 + 8) * 64 + nA], W2[(size_t)(k0 + 9) * 64 + nA]));
            v.z = h2u(__floats2half2_rn(W2[(size_t)k0 * 64 + nB], W2[(size_t)(k0 + 1) * 64 + nB]));
            v.w = h2u(__floats2half2_rn(W2[(size_t)(k0 + 8) * 64 + nB], W2[(size_t)(k0 + 9) * 64 + nB]));
            g_w2f[u] = v;
        }
    }

    const int i = t >> 4, d4 = t & 15;
    const int id  = __ldg(item_ids + i);
    const int len = __ldg(tag_lens + i);
    const int4 tg0 = __ldg((const int4*)(tag_ids + (size_t)i * 8));
    const int4 tg1 = __ldg((const int4*)(tag_ids + (size_t)i * 8) + 1);
    const int tg[8] = {tg0.x, tg0.y, tg0.z, tg0.w, tg1.x, tg1.y, tg1.z, tg1.w};

    const float4 ei = __ldg((const float4*)(item_table + (size_t)id * 64) + d4);
    const float4 ed = __ldg((const float4*)(dat_table + (size_t)id * 64) + d4);

    const float4 z4 = make_float4(0.f, 0.f, 0.f, 0.f);
    float4 tv[8];
    #pragma unroll
    for (int j = 0; j < 8; j++)
        tv[j] = (j < len) ? __ldg((const float4*)(tag_table + (size_t)tg[j] * 64) + d4) : z4;

    float4 sum = make_float4(0.f, 0.f, 0.f, 0.f);
    #pragma unroll
    for (int j = 0; j < 8; j++) {
        sum.x += tv[j].x; sum.y += tv[j].y; sum.z += tv[j].z; sum.w += tv[j].w;
    }
    const float inv = 1.0f / (float)len;

    ((float4*)(out + (size_t)NI * 64 + (size_t)i * 64))[d4] = ed;
    uint2* xrow = (uint2*)(g_x + (size_t)i * 256);
    xrow[d4] = pack_h4(ei);
    xrow[16 + d4] = pack_h4(make_float4(sum.x * inv, sum.y * inv, sum.z * inv, sum.w * inv));
}

// ---- kernel B: barrier-free register-resident tower ----
// Each warp owns 16 item rows end-to-end. GEMM1 C-frags are relu'd and packed
// in-register into GEMM2 A-frags (identical lane layout), so H never touches smem.
__global__ __launch_bounds__(NTHREADS, 4)
void gemm_tower(const float* __restrict__ b1,
                const float* __restrict__ b2,
                float* __restrict__ out)
{
    extern __shared__ __align__(128) char sm[];
    const uint32_t smb = smem_u32(sm);
    const int tid = threadIdx.x;
    const int lane = tid & 31;
    const int wid = tid >> 5;            // 0..3 -> rows [16w, 16w+16)
    const int gi0 = blockIdx.x * IPB;

    float* b1s = (float*)(sm + META);          // [256]
    float* b2s = (float*)(sm + META + 1024);   // [64]

    // ---- DMA X tile into swizzled smem ----
    {
        const uint64_t src = gmem_u64(g_x) + (size_t)gi0 * 256;
        #pragma unroll
        for (int j = 0; j < 8; j++) {
            const int c = tid + j * NTHREADS;          // 1024 chunks of 16B
            const int m = c >> 4, c16 = c & 15;
            cp16(smb + XHO + (uint32_t)(m * 256 + ((c16 * 16) ^ ((m & 7) * 16))),
                 src + c * 16);
        }
        CP_COMMIT();
    }
    b1s[tid] = b1[tid];
    b1s[tid + 128] = b1[tid + 128];
    if (tid < 64) b2s[tid] = b2[tid];
    CP_WAIT0();
    __syncthreads();                     // the ONLY barrier

    const int m0 = wid * 16;
    uint32_t Hf[16][4];                  // GEMM2 A-frags, built in-register

    // ---- GEMM1 in four n-groups of 64; pack C -> Hf ----
    #pragma unroll
    for (int g = 0; g < 4; g++) {
        float acc[8][4];
        #pragma unroll
        for (int j = 0; j < 8; j++)
            #pragma unroll
            for (int q = 0; q < 4; q++) acc[j][q] = 0.f;

        #pragma unroll
        for (int kt = 0; kt < 8; kt++) {
            uint32_t A[4];
            ldm_x4(A, smb + XHO + xoff(m0 + (lane & 15), kt * 16 + ((lane >> 4) << 3)));
            #pragma unroll
            for (int np = 0; np < 4; np++) {
                const uint4 v = __ldg(g_w1f + ((kt * 16 + g * 4 + np) * 32 + lane));
                mma16816h(acc[np * 2], A, v.x, v.y);
                mma16816h(acc[np * 2 + 1], A, v.z, v.w);
            }
        }
        // relu + bias -> A-fragments of k-tiles [4g, 4g+4)
        #pragma unroll
        for (int j = 0; j < 8; j++) {
            const int ncol = g * 64 + j * 8 + 2 * (lane & 3);
            const float2 bias = *(const float2*)(b1s + ncol);
            const float f0 = fmaxf(acc[j][0] + bias.x, 0.f);
            const float f1 = fmaxf(acc[j][1] + bias.y, 0.f);
            const float f2 = fmaxf(acc[j][2] + bias.x, 0.f);
            const float f3 = fmaxf(acc[j][3] + bias.y, 0.f);
            const int tk = g * 4 + (j >> 1);
            const int hi = (j & 1) * 2;          // even n-tile -> a0,a1 ; odd -> a2,a3
            Hf[tk][hi]     = h2u(__floats2half2_rn(f0, f1));
            Hf[tk][hi + 1] = h2u(__floats2half2_rn(f2, f3));
        }
    }

    // ---- GEMM2: O[16,64] = H @ W2, A straight from registers ----
    float acc2[8][4];
    #pragma unroll
    for (int j = 0; j < 8; j++)
        #pragma unroll
        for (int q = 0; q < 4; q++) acc2[j][q] = 0.f;

    #pragma unroll
    for (int tk = 0; tk < 16; tk++) {
        #pragma unroll
        for (int np = 0; np < 4; np++) {
            const uint4 v = __ldg(g_w2f + ((tk * 4 + np) * 32 + lane));
            mma16816h(acc2[np * 2], Hf[tk], v.x, v.y);
            mma16816h(acc2[np * 2 + 1], Hf[tk], v.z, v.w);
        }
    }

    // ---- epilogue: out = O + b2 ----
    #pragma unroll
    for (int j = 0; j < 8; j++) {
        const int n = j * 8 + 2 * (lane & 3);
        const float2 bias = *(const float2*)(b2s + n);
        const int r = gi0 + m0 + (lane >> 2);
        *(float2*)(out + (size_t)r * 64 + n) =
            make_float2(acc2[j][0] + bias.x, acc2[j][1] + bias.y);
        *(float2*)(out + (size_t)(r + 8) * 64 + n) =
            make_float2(acc2[j][2] + bias.x, acc2[j][3] + bias.y);
    }
}

extern "C" void kernel_launch(void* const* d_in, const int* in_sizes, int n_in,
                              void* d_out, int out_size) {
    cudaFuncSetAttribute(gemm_tower,
                         cudaFuncAttributeMaxDynamicSharedMemorySize, SMEM_BYTES);
    gather_kernel<<<NI * 16 / 256, 256>>>(
        (const int*)d_in[0], (const int*)d_in[1], (const int*)d_in[2],
        (const float*)d_in[3], (const float*)d_in[4], (const float*)d_in[5],
        (const float*)d_in[6], (const float*)d_in[8],
        (float*)d_out);
    gemm_tower<<<NBLK, NTHREADS, SMEM_BYTES>>>(
        (const float*)d_in[7], (const float*)d_in[9], (float*)d_out);
}

// round 11
// speedup vs baseline: 1.0805x; 1.0805x over previous
#include <cuda_runtime.h>
#include <cuda_fp16.h>
#include <cstdint>

#define NI 16384
#define IPB 64
#define NTHREADS 128
#define NBLK (NI / IPB)

// gemm kernel smem: X[64m][128k]f16 16KB @0, then b1/b2
#define XHO  0u
#define META 16384u
#define SMEM_BYTES 17664

__device__ uint4 g_w1f[4096];                         // W1 mma-B fragment image
__device__ uint4 g_w2f[2048];                         // W2 mma-B fragment image
__device__ __align__(16) unsigned char g_x[NI * 256]; // X rows, fp16 [16384][128]

static __device__ __forceinline__ uint32_t smem_u32(const void* p) {
    uint32_t a;
    asm("{ .reg .u64 t; cvta.to.shared.u64 t, %1; cvt.u32.u64 %0, t; }" : "=r"(a) : "l"(p));
    return a;
}
static __device__ __forceinline__ uint64_t gmem_u64(const void* p) {
    uint64_t a;
    asm("cvta.to.global.u64 %0, %1;" : "=l"(a) : "l"(p));
    return a;
}
static __device__ __forceinline__ uint32_t xoff(int m, int k) {   // 256B rows, swizzled
    return (uint32_t)(m * 256 + ((k * 2) ^ ((m & 7) * 16)));
}
static __device__ __forceinline__ uint32_t h2u(__half2 v) {
    return *reinterpret_cast<uint32_t*>(&v);
}
static __device__ __forceinline__ uint2 pack_h4(float4 v) {
    return make_uint2(h2u(__floats2half2_rn(v.x, v.y)), h2u(__floats2half2_rn(v.z, v.w)));
}
static __device__ __forceinline__ void cp16(uint32_t dst, uint64_t src) {
    asm volatile("cp.async.cg.shared.global [%0], [%1], 16;" :: "r"(dst), "l"(src) : "memory");
}
#define CP_COMMIT() asm volatile("cp.async.commit_group;" ::: "memory")
#define CP_WAIT0()  asm volatile("cp.async.wait_group 0;" ::: "memory")

static __device__ __forceinline__ void ldm_x4(uint32_t* r, uint32_t a) {
    asm volatile("ldmatrix.sync.aligned.m8n8.x4.shared.b16 {%0,%1,%2,%3}, [%4];"
        : "=r"(r[0]), "=r"(r[1]), "=r"(r[2]), "=r"(r[3]) : "r"(a));
}
static __device__ __forceinline__ void mma16816h(float* c, const uint32_t* a,
                                                 uint32_t b0, uint32_t b1) {
    asm volatile("mma.sync.aligned.m16n8k16.row.col.f32.f16.f16.f32 "
        "{%0,%1,%2,%3}, {%4,%5,%6,%7}, {%8,%9}, {%0,%1,%2,%3};"
        : "+f"(c[0]), "+f"(c[1]), "+f"(c[2]), "+f"(c[3])
        : "r"(a[0]), "r"(a[1]), "r"(a[2]), "r"(a[3]), "r"(b0), "r"(b1));
}

// ---- kernel A: streaming gather + (first 6144 threads) weight frag build ----
__global__ __launch_bounds__(256)
void gather_kernel(const int* __restrict__ item_ids,
                   const int* __restrict__ tag_ids,
                   const int* __restrict__ tag_lens,
                   const float* __restrict__ item_table,
                   const float* __restrict__ dat_table,
                   const float* __restrict__ tag_table,
                   const float* __restrict__ W1,
                   const float* __restrict__ W2,
                   float* __restrict__ out)
{
    const int t = blockIdx.x * 256 + threadIdx.x;   // 0 .. 262143

    if (t < 6144) {
        if (t < 4096) {
            const int kt = t >> 9, rem = t & 511;
            const int p = rem >> 5, lane = rem & 31;
            const int k0 = kt * 16 + (lane & 3) * 2;
            const int nA = p * 16 + (lane >> 2), nB = nA + 8;
            uint4 v;
            v.x = h2u(__floats2half2_rn(W1[(size_t)k0 * 256 + nA], W1[(size_t)(k0 + 1) * 256 + nA]));
            v.y = h2u(__floats2half2_rn(W1[(size_t)(k0 + 8) * 256 + nA], W1[(size_t)(k0 + 9) * 256 + nA]));
            v.z = h2u(__floats2half2_rn(W1[(size_t)k0 * 256 + nB], W1[(size_t)(k0 + 1) * 256 + nB]));
            v.w = h2u(__floats2half2_rn(W1[(size_t)(k0 + 8) * 256 + nB], W1[(size_t)(k0 + 9) * 256 + nB]));
            g_w1f[t] = v;
        } else {
            const int u = t - 4096;
            const int kt = u >> 7, rem = u & 127;
            const int p = rem >> 5, lane = rem & 31;
            const int k0 = kt * 16 + (lane & 3) * 2;
            const int nA = p * 16 + (lane >> 2), nB = nA + 8;
            uint4 v;
            v.x = h2u(__floats2half2_rn(W2[(size_t)k0 * 64 + nA], W2[(size_t)(k0 + 1) * 64 + nA]));
            v.y = h2u(__floats2half2_rn(W2[(size_t)(k0 + 8) * 64 + nA], W2[(size_t)(k0 + 9) * 64 + nA]));
            v.z = h2u(__floats2half2_rn(W2[(size_t)k0 * 64 + nB], W2[(size_t)(k0 + 1) * 64 + nB]));
            v.w = h2u(__floats2half2_rn(W2[(size_t)(k0 + 8) * 64 + nB], W2[(size_t)(k0 + 9) * 64 + nB]));
            g_w2f[u] = v;
        }
    }

    const int i = t >> 4, d4 = t & 15;
    const int id  = __ldg(item_ids + i);
    const int len = __ldg(tag_lens + i);
    const int4 tg0 = __ldg((const int4*)(tag_ids + (size_t)i * 8));
    const int4 tg1 = __ldg((const int4*)(tag_ids + (size_t)i * 8) + 1);
    const int tg[8] = {tg0.x, tg0.y, tg0.z, tg0.w, tg1.x, tg1.y, tg1.z, tg1.w};

    const float4 ei = __ldg((const float4*)(item_table + (size_t)id * 64) + d4);
    const float4 ed = __ldg((const float4*)(dat_table + (size_t)id * 64) + d4);

    const float4 z4 = make_float4(0.f, 0.f, 0.f, 0.f);
    float4 tv[8];
    #pragma unroll
    for (int j = 0; j < 8; j++)
        tv[j] = (j < len) ? __ldg((const float4*)(tag_table + (size_t)tg[j] * 64) + d4) : z4;

    float4 sum = make_float4(0.f, 0.f, 0.f, 0.f);
    #pragma unroll
    for (int j = 0; j < 8; j++) {
        sum.x += tv[j].x; sum.y += tv[j].y; sum.z += tv[j].z; sum.w += tv[j].w;
    }
    const float inv = 1.0f / (float)len;

    ((float4*)(out + (size_t)NI * 64 + (size_t)i * 64))[d4] = ed;
    uint2* xrow = (uint2*)(g_x + (size_t)i * 256);
    xrow[d4] = pack_h4(ei);
    xrow[16 + d4] = pack_h4(make_float4(sum.x * inv, sum.y * inv, sum.z * inv, sum.w * inv));
}

// ---- kernel B: barrier-free tower, GEMM2 interleaved per GEMM1 n-group ----
// Each warp owns 16 rows. GEMM1 group g (64 cols) produces H k-tiles [4g,4g+4);
// they are relu'd, packed into transient A-frags, folded into acc2, discarded.
__global__ __launch_bounds__(NTHREADS, 4)
void gemm_tower(const float* __restrict__ b1,
                const float* __restrict__ b2,
                float* __restrict__ out)
{
    extern __shared__ __align__(128) char sm[];
    const uint32_t smb = smem_u32(sm);
    const int tid = threadIdx.x;
    const int lane = tid & 31;
    const int wid = tid >> 5;            // 0..3 -> rows [16w, 16w+16)
    const int gi0 = blockIdx.x * IPB;

    float* b1s = (float*)(sm + META);          // [256]
    float* b2s = (float*)(sm + META + 1024);   // [64]

    // ---- DMA X tile into swizzled smem ----
    {
        const uint64_t src = gmem_u64(g_x) + (size_t)gi0 * 256;
        #pragma unroll
        for (int j = 0; j < 8; j++) {
            const int c = tid + j * NTHREADS;          // 1024 chunks of 16B
            const int m = c >> 4, c16 = c & 15;
            cp16(smb + XHO + (uint32_t)(m * 256 + ((c16 * 16) ^ ((m & 7) * 16))),
                 src + c * 16);
        }
        CP_COMMIT();
    }
    b1s[tid] = b1[tid];
    b1s[tid + 128] = b1[tid + 128];
    if (tid < 64) b2s[tid] = b2[tid];
    CP_WAIT0();
    __syncthreads();                     // the ONLY barrier

    const int m0 = wid * 16;

    float acc2[8][4];
    #pragma unroll
    for (int j = 0; j < 8; j++)
        #pragma unroll
        for (int q = 0; q < 4; q++) acc2[j][q] = 0.f;

    #pragma unroll
    for (int g = 0; g < 4; g++) {
        // ---- GEMM1 n-group g: C[16,64] over full K=128 ----
        float acc[8][4];
        #pragma unroll
        for (int j = 0; j < 8; j++)
            #pragma unroll
            for (int q = 0; q < 4; q++) acc[j][q] = 0.f;

        #pragma unroll
        for (int kt = 0; kt < 8; kt++) {
            uint32_t A[4];
            ldm_x4(A, smb + XHO + xoff(m0 + (lane & 15), kt * 16 + ((lane >> 4) << 3)));
            #pragma unroll
            for (int np = 0; np < 4; np++) {
                const uint4 v = __ldg(g_w1f + ((kt * 16 + g * 4 + np) * 32 + lane));
                mma16816h(acc[np * 2], A, v.x, v.y);
                mma16816h(acc[np * 2 + 1], A, v.z, v.w);
            }
        }

        // ---- relu + bias -> transient A-frags Hf4 (H k-tiles 4g..4g+3) ----
        uint32_t Hf4[4][4];
        #pragma unroll
        for (int j = 0; j < 8; j++) {
            const int ncol = g * 64 + j * 8 + 2 * (lane & 3);
            const float2 bias = *(const float2*)(b1s + ncol);
            const float f0 = fmaxf(acc[j][0] + bias.x, 0.f);
            const float f1 = fmaxf(acc[j][1] + bias.y, 0.f);
            const float f2 = fmaxf(acc[j][2] + bias.x, 0.f);
            const float f3 = fmaxf(acc[j][3] + bias.y, 0.f);
            const int tk = j >> 1;
            const int hi = (j & 1) * 2;          // even n-tile -> a0,a1 ; odd -> a2,a3
            Hf4[tk][hi]     = h2u(__floats2half2_rn(f0, f1));
            Hf4[tk][hi + 1] = h2u(__floats2half2_rn(f2, f3));
        }

        // ---- fold into GEMM2: acc2 += Hf4[tk] * W2[k-tiles 4g+tk] ----
        #pragma unroll
        for (int tk = 0; tk < 4; tk++) {
            const int ktg = g * 4 + tk;
            #pragma unroll
            for (int np = 0; np < 4; np++) {
                const uint4 v = __ldg(g_w2f + ((ktg * 4 + np) * 32 + lane));
                mma16816h(acc2[np * 2], Hf4[tk], v.x, v.y);
                mma16816h(acc2[np * 2 + 1], Hf4[tk], v.z, v.w);
            }
        }
    }

    // ---- epilogue: out = O + b2 ----
    #pragma unroll
    for (int j = 0; j < 8; j++) {
        const int n = j * 8 + 2 * (lane & 3);
        const float2 bias = *(const float2*)(b2s + n);
        const int r = gi0 + m0 + (lane >> 2);
        *(float2*)(out + (size_t)r * 64 + n) =
            make_float2(acc2[j][0] + bias.x, acc2[j][1] + bias.y);
        *(float2*)(out + (size_t)(r + 8) * 64 + n) =
            make_float2(acc2[j][2] + bias.x, acc2[j][3] + bias.y);
    }
}

extern "C" void kernel_launch(void* const* d_in, const int* in_sizes, int n_in,
                              void* d_out, int out_size) {
    cudaFuncSetAttribute(gemm_tower,
                         cudaFuncAttributeMaxDynamicSharedMemorySize, SMEM_BYTES);
    gather_kernel<<<NI * 16 / 256, 256>>>(
        (const int*)d_in[0], (const int*)d_in[1], (const int*)d_in[2],
        (const float*)d_in[3], (const float*)d_in[4], (const float*)d_in[5],
        (const float*)d_in[6], (const float*)d_in[8],
        (float*)d_out);
    gemm_tower<<<NBLK, NTHREADS, SMEM_BYTES>>>(
        (const float*)d_in[7], (const float*)d_in[9], (float*)d_out);
}

// round 13
// speedup vs baseline: 1.6023x; 1.4830x over previous
#include <cuda_runtime.h>
#include <cuda_fp16.h>
#include <cstdint>

#define NI 16384
#define IPB 32
#define NTHREADS 256
#define NBLK (NI / IPB)

// gemm kernel smem: X[32m][128k]f16 8KB @0; H[32m][256k]f16 16KB @0 (reuse); meta @16K
#define XHO  0u
#define HHO  0u
#define META 16384u
#define SMEM_BYTES 17664

__device__ uint4 g_w1f[4096];                         // W1 mma-B fragment image
__device__ uint4 g_w2f[2048];                         // W2 mma-B fragment image
__device__ __align__(16) unsigned char g_x[NI * 256]; // X rows, fp16 [16384][128]

static __device__ __forceinline__ uint32_t smem_u32(const void* p) {
    uint32_t a;
    asm("{ .reg .u64 t; cvta.to.shared.u64 t, %1; cvt.u32.u64 %0, t; }" : "=r"(a) : "l"(p));
    return a;
}
static __device__ __forceinline__ uint64_t gmem_u64(const void* p) {
    uint64_t a;
    asm("cvta.to.global.u64 %0, %1;" : "=l"(a) : "l"(p));
    return a;
}
static __device__ __forceinline__ uint32_t xoff(int m, int k) {   // 256B rows, swizzled
    return (uint32_t)(m * 256 + ((k * 2) ^ ((m & 7) * 16)));
}
static __device__ __forceinline__ uint32_t hoff(int m, int k) {   // 512B rows, swizzled
    return (uint32_t)(m * 512 + ((k * 2) ^ ((m & 7) * 16)));
}
static __device__ __forceinline__ uint32_t h2u(__half2 v) {
    return *reinterpret_cast<uint32_t*>(&v);
}
static __device__ __forceinline__ void st_h2(char* sm, uint32_t o, float a, float b) {
    *(uint32_t*)(sm + o) = h2u(__floats2half2_rn(a, b));
}
static __device__ __forceinline__ uint2 pack_h4(float4 v) {
    return make_uint2(h2u(__floats2half2_rn(v.x, v.y)), h2u(__floats2half2_rn(v.z, v.w)));
}
static __device__ __forceinline__ void cp16(uint32_t dst, uint64_t src) {
    asm volatile("cp.async.cg.shared.global [%0], [%1], 16;" :: "r"(dst), "l"(src) : "memory");
}
#define CP_COMMIT() asm volatile("cp.async.commit_group;" ::: "memory")
#define CP_WAIT0()  asm volatile("cp.async.wait_group 0;" ::: "memory")

static __device__ __forceinline__ void ldm_x4(uint32_t* r, uint32_t a) {
    asm volatile("ldmatrix.sync.aligned.m8n8.x4.shared.b16 {%0,%1,%2,%3}, [%4];"
        : "=r"(r[0]), "=r"(r[1]), "=r"(r[2]), "=r"(r[3]) : "r"(a));
}
static __device__ __forceinline__ void mma16816h(float* c, const uint32_t* a,
                                                 uint32_t b0, uint32_t b1) {
    asm volatile("mma.sync.aligned.m16n8k16.row.col.f32.f16.f16.f32 "
        "{%0,%1,%2,%3}, {%4,%5,%6,%7}, {%8,%9}, {%0,%1,%2,%3};"
        : "+f"(c[0]), "+f"(c[1]), "+f"(c[2]), "+f"(c[3])
        : "r"(a[0]), "r"(a[1]), "r"(a[2]), "r"(a[3]), "r"(b0), "r"(b1));
}

// ---- kernel A: streaming gather + (first 6144 threads) weight frag build ----
__global__ __launch_bounds__(256)
void gather_kernel(const int* __restrict__ item_ids,
                   const int* __restrict__ tag_ids,
                   const int* __restrict__ tag_lens,
                   const float* __restrict__ item_table,
                   const float* __restrict__ dat_table,
                   const float* __restrict__ tag_table,
                   const float* __restrict__ W1,
                   const float* __restrict__ W2,
                   float* __restrict__ out)
{
    const int t = blockIdx.x * 256 + threadIdx.x;   // 0 .. 262143

    if (t < 6144) {
        if (t < 4096) {
            const int kt = t >> 9, rem = t & 511;
            const int p = rem >> 5, lane = rem & 31;
            const int k0 = kt * 16 + (lane & 3) * 2;
            const int nA = p * 16 + (lane >> 2), nB = nA + 8;
            uint4 v;
            v.x = h2u(__floats2half2_rn(W1[(size_t)k0 * 256 + nA], W1[(size_t)(k0 + 1) * 256 + nA]));
            v.y = h2u(__floats2half2_rn(W1[(size_t)(k0 + 8) * 256 + nA], W1[(size_t)(k0 + 9) * 256 + nA]));
            v.z = h2u(__floats2half2_rn(W1[(size_t)k0 * 256 + nB], W1[(size_t)(k0 + 1) * 256 + nB]));
            v.w = h2u(__floats2half2_rn(W1[(size_t)(k0 + 8) * 256 + nB], W1[(size_t)(k0 + 9) * 256 + nB]));
            g_w1f[t] = v;
        } else {
            const int u = t - 4096;
            const int kt = u >> 7, rem = u & 127;
            const int p = rem >> 5, lane = rem & 31;
            const int k0 = kt * 16 + (lane & 3) * 2;
            const int nA = p * 16 + (lane >> 2), nB = nA + 8;
            uint4 v;
            v.x = h2u(__floats2half2_rn(W2[(size_t)k0 * 64 + nA], W2[(size_t)(k0 + 1) * 64 + nA]));
            v.y = h2u(__floats2half2_rn(W2[(size_t)(k0 + 8) * 64 + nA], W2[(size_t)(k0 + 9) * 64 + nA]));
            v.z = h2u(__floats2half2_rn(W2[(size_t)k0 * 64 + nB], W2[(size_t)(k0 + 1) * 64 + nB]));
            v.w = h2u(__floats2half2_rn(W2[(size_t)(k0 + 8) * 64 + nB], W2[(size_t)(k0 + 9) * 64 + nB]));
            g_w2f[u] = v;
        }
    }

    const int i = t >> 4, d4 = t & 15;
    const int id  = __ldg(item_ids + i);
    const int len = __ldg(tag_lens + i);
    const int4 tg0 = __ldg((const int4*)(tag_ids + (size_t)i * 8));
    const int4 tg1 = __ldg((const int4*)(tag_ids + (size_t)i * 8) + 1);
    const int tg[8] = {tg0.x, tg0.y, tg0.z, tg0.w, tg1.x, tg1.y, tg1.z, tg1.w};

    const float4 ei = __ldg((const float4*)(item_table + (size_t)id * 64) + d4);
    const float4 ed = __ldg((const float4*)(dat_table + (size_t)id * 64) + d4);

    const float4 z4 = make_float4(0.f, 0.f, 0.f, 0.f);
    float4 tv[8];
    #pragma unroll
    for (int j = 0; j < 8; j++)
        tv[j] = (j < len) ? __ldg((const float4*)(tag_table + (size_t)tg[j] * 64) + d4) : z4;

    float4 sum = make_float4(0.f, 0.f, 0.f, 0.f);
    #pragma unroll
    for (int j = 0; j < 8; j++) {
        sum.x += tv[j].x; sum.y += tv[j].y; sum.z += tv[j].z; sum.w += tv[j].w;
    }
    const float inv = 1.0f / (float)len;

    ((float4*)(out + (size_t)NI * 64 + (size_t)i * 64))[d4] = ed;
    uint2* xrow = (uint2*)(g_x + (size_t)i * 256);
    xrow[d4] = pack_h4(ei);
    xrow[16 + d4] = pack_h4(make_float4(sum.x * inv, sum.y * inv, sum.z * inv, sum.w * inv));
}

// ---- kernel B: 32-item tile, 8 warps, software-pipelined B loads ----
__global__ __launch_bounds__(NTHREADS, 2)
void gemm_tower(const float* __restrict__ b1,
                const float* __restrict__ b2,
                float* __restrict__ out)
{
    extern __shared__ __align__(128) char sm[];
    const uint32_t smb = smem_u32(sm);
    const int tid = threadIdx.x;
    const int lane = tid & 31;
    const int wid = tid >> 5;
    const int gi0 = blockIdx.x * IPB;

    float* b1s = (float*)(sm + META);          // [256]
    float* b2s = (float*)(sm + META + 1024);   // [64]

    // ---- DMA X tile (32 rows) into swizzled smem ----
    {
        const uint64_t src = gmem_u64(g_x) + (size_t)gi0 * 256;
        #pragma unroll
        for (int j = 0; j < 2; j++) {
            const int c = tid + j * NTHREADS;          // 512 chunks of 16B
            const int m = c >> 4, c16 = c & 15;
            cp16(smb + XHO + (uint32_t)(m * 256 + ((c16 * 16) ^ ((m & 7) * 16))),
                 src + c * 16);
        }
        CP_COMMIT();
    }
    b1s[tid] = b1[tid];
    if (tid < 64) b2s[tid] = b2[tid];
    CP_WAIT0();
    __syncthreads();

    const int m0 = (wid >> 2) * 16;       // warp m-tile (16 rows)
    const int gq = wid & 3;               // warp n-group (64 cols)

    // ---- GEMM1: C[16,64] = X @ W1, pipelined ----
    float acc[8][4];
    #pragma unroll
    for (int j = 0; j < 8; j++)
        #pragma unroll
        for (int q = 0; q < 4; q++) acc[j][q] = 0.f;

    uint32_t A[4];
    uint4 vb[4];
    ldm_x4(A, smb + XHO + xoff(m0 + (lane & 15), (lane >> 4) << 3));
    #pragma unroll
    for (int np = 0; np < 4; np++)
        vb[np] = __ldg(g_w1f + ((gq * 4 + np) * 32 + lane));

    #pragma unroll
    for (int kt = 0; kt < 8; kt++) {
        uint32_t Ac[4] = {A[0], A[1], A[2], A[3]};
        uint4 bc[4] = {vb[0], vb[1], vb[2], vb[3]};
        if (kt < 7) {
            ldm_x4(A, smb + XHO + xoff(m0 + (lane & 15), (kt + 1) * 16 + ((lane >> 4) << 3)));
            #pragma unroll
            for (int np = 0; np < 4; np++)
                vb[np] = __ldg(g_w1f + (((kt + 1) * 16 + gq * 4 + np) * 32 + lane));
        }
        #pragma unroll
        for (int np = 0; np < 4; np++) {
            mma16816h(acc[np * 2], Ac, bc[np].x, bc[np].y);
            mma16816h(acc[np * 2 + 1], Ac, bc[np].z, bc[np].w);
        }
    }
    __syncthreads();    // all warps done reading X before H overwrites it

    // ---- H = relu(C + b1) -> fp16 smem (rows m0..m0+16, cols gq*64..+64) ----
    #pragma unroll
    for (int j = 0; j < 8; j++) {
        const int ncol = gq * 64 + j * 8 + 2 * (lane & 3);
        const float2 bias = *(const float2*)(b1s + ncol);
        const int r = m0 + (lane >> 2);
        st_h2(sm, HHO + hoff(r, ncol),
              fmaxf(acc[j][0] + bias.x, 0.f), fmaxf(acc[j][1] + bias.y, 0.f));
        st_h2(sm, HHO + hoff(r + 8, ncol),
              fmaxf(acc[j][2] + bias.x, 0.f), fmaxf(acc[j][3] + bias.y, 0.f));
    }
    __syncthreads();

    // ---- GEMM2: O[16,16] per warp = H @ W2, pipelined ----
    const int m2 = (wid >> 2) * 16;
    const int p = wid & 3;                // 16-col slice
    float acc2[2][4];
    #pragma unroll
    for (int j = 0; j < 2; j++)
        #pragma unroll
        for (int q = 0; q < 4; q++) acc2[j][q] = 0.f;

    uint32_t A2[4];
    uint4 v2;
    ldm_x4(A2, smb + HHO + hoff(m2 + (lane & 15), (lane >> 4) << 3));
    v2 = __ldg(g_w2f + (p * 32 + lane));

    #pragma unroll
    for (int kt = 0; kt < 16; kt++) {
        uint32_t Ac[4] = {A2[0], A2[1], A2[2], A2[3]};
        const uint4 bc = v2;
        if (kt < 15) {
            ldm_x4(A2, smb + HHO + hoff(m2 + (lane & 15), (kt + 1) * 16 + ((lane >> 4) << 3)));
            v2 = __ldg(g_w2f + (((kt + 1) * 4 + p) * 32 + lane));
        }
        mma16816h(acc2[0], Ac, bc.x, bc.y);
        mma16816h(acc2[1], Ac, bc.z, bc.w);
    }

    // ---- epilogue: out = O + b2 ----
    #pragma unroll
    for (int j = 0; j < 2; j++) {
        const int n = p * 16 + j * 8 + 2 * (lane & 3);
        const float2 bias = *(const float2*)(b2s + n);
        const int r = gi0 + m2 + (lane >> 2);
        *(float2*)(out + (size_t)r * 64 + n) =
            make_float2(acc2[j][0] + bias.x, acc2[j][1] + bias.y);
        *(float2*)(out + (size_t)(r + 8) * 64 + n) =
            make_float2(acc2[j][2] + bias.x, acc2[j][3] + bias.y);
    }
}

extern "C" void kernel_launch(void* const* d_in, const int* in_sizes, int n_in,
                              void* d_out, int out_size) {
    cudaFuncSetAttribute(gemm_tower,
                         cudaFuncAttributeMaxDynamicSharedMemorySize, SMEM_BYTES);
    gather_kernel<<<NI * 16 / 256, 256>>>(
        (const int*)d_in[0], (const int*)d_in[1], (const int*)d_in[2],
        (const float*)d_in[3], (const float*)d_in[4], (const float*)d_in[5],
        (const float*)d_in[6], (const float*)d_in[8],
        (float*)d_out);
    gemm_tower<<<NBLK, NTHREADS, SMEM_BYTES>>>(
        (const float*)d_in[7], (const float*)d_in[9], (float*)d_out);
}